// round 14
// baseline (speedup 1.0000x reference)
#include <cuda_runtime.h>

// ---------------------------------------------------------------------------
// CMIAttentionMatrixForAcrobot, restructured:
//   T[j,i]   = sum_n data_q[n,i] * W_lin[j,n]            (phase1 splitk -> red.v4 g_T)
//   k[j,m]   = sum_i data_k[j,i] * W_k[m,i] + b_k[m]     (phase1 rowgemv, slot0)
//   nq[m,j]  = sum_i W_q[m,i] * T[j,i] + b_q[m]*slin[j] + b_lin[j]   (phase2 A)
//   kmod     = relu6(k^2 + 2k + nq*(1+|k|))              (phase2 B)
//   v[j,i]   = sum_m W_q[m,i] * kmod[j,m]                (phase2 C -> red.v4 g_v;
//                                                         W_q re-read hits L2)
//   c[j]     = sum_m b_q[m] * kmod[j,m]                  (phase2 partials)
//   out[n,j] = (sum_i data_q[n,i] * v[j,i] + c[j]) / 64  (dot rowgemv + epi B)
// phase2 reads W_q from DRAM ONCE (sweep C re-reads from L2: 128 concurrent
// blocks x 512KB = full 64MB W_q < 126MB L2). Saves a whole 64MB DRAM pass.
// g_T/g_v zero-invariant maintained by epilogueB's tail. 5 launches.
// ---------------------------------------------------------------------------

typedef unsigned long long u64;

#define N_DIM 4096
#define JD 6
#define NTHR 256

// T splitk: 64 rows x 1024 cols per block
#define RPS_T 64
#define NSPLIT_T 64
#define SPLITK_T_BLOCKS (4 * NSPLIT_T)    // 256

// row-GEMV: 16 rows (8 warps x 2 rows) x 512 cols per block
#define KSPLIT 8
#define CPK (N_DIM / KSPLIT)              // 512
#define RGROWS 16
#define RGX (N_DIM / RGROWS)              // 256
#define RG_BLOCKS (RGX * KSPLIT)          // 2048

// phase2: 128 blocks x 512 threads x 32 rows
#define P2_BLOCKS 128
#define P2_ROWS 32

#define EPIB_BLOCKS 32

// scratch (static device globals; zero-initialized at module load)
__device__ float g_T[JD * N_DIM];
__device__ float g_v[JD * N_DIM];
__device__ float g_rgpart[2 * KSPLIT * N_DIM * JD];   // slot0: k then dot; slot1 unused
__device__ float g_cpart[P2_BLOCKS * JD];
__device__ float g_slin[JD];

// ---- packed fp32x2 helpers ------------------------------------------------
__device__ __forceinline__ u64 pk2(float a, float b) {
    u64 r;
    asm("mov.b64 %0, {%1, %2};" : "=l"(r) : "r"(__float_as_uint(a)), "r"(__float_as_uint(b)));
    return r;
}
__device__ __forceinline__ float2 upk(u64 v) {
    unsigned lo, hi;
    asm("mov.b64 {%0, %1}, %2;" : "=r"(lo), "=r"(hi) : "l"(v));
    return make_float2(__uint_as_float(lo), __uint_as_float(hi));
}
__device__ __forceinline__ void fma2(u64& d, u64 a, u64 b) {
    asm("fma.rn.f32x2 %0, %1, %2, %0;" : "+l"(d) : "l"(a), "l"(b));
}
__device__ __forceinline__ void add2(u64& d, u64 a) {
    asm("add.rn.f32x2 %0, %0, %1;" : "+l"(d) : "l"(a));
}
// vectored global float reduction (sm_90+), 4 floats per op
__device__ __forceinline__ void red4(float* gp, float a, float b, float c, float d) {
    asm volatile(
        "{\n\t.reg .u64 p;\n\t"
        "cvta.to.global.u64 p, %0;\n\t"
        "red.global.add.v4.f32 [p], {%1, %2, %3, %4};\n\t}"
        :: "l"(gp), "f"(a), "f"(b), "f"(c), "f"(d) : "memory");
}

// --------------------------------------------------------------------------
// phase-1 bodies (256-thread blocks) — identical to the 92.9us baseline
// --------------------------------------------------------------------------
__device__ __forceinline__ void slin_body(const float* __restrict__ Wlin) {
    const int wid = threadIdx.x >> 5;
    const int lane = threadIdx.x & 31;
    if (wid < JD) {
        const float4* p = (const float4*)(Wlin + wid * N_DIM);
        float s = 0.0f;
        for (int q = lane; q < N_DIM / 4; q += 32) {
            float4 v = p[q];
            s += v.x + v.y + v.z + v.w;
        }
        #pragma unroll
        for (int o = 16; o; o >>= 1) s += __shfl_xor_sync(0xffffffffu, s, o);
        if (lane == 0) g_slin[wid] = s;
    }
}

template<int RPS_>
__device__ __forceinline__ void splitk_body(const float* __restrict__ big,
                                            const float* __restrict__ w,
                                            float* __restrict__ out,
                                            int cslab, int split,
                                            float (*ws)[RPS_]) {
    const int tid = threadIdx.x;
    const int c0 = cslab * 1024 + tid * 4;
    const int r0 = split * RPS_;

    for (int idx = tid; idx < JD * RPS_; idx += NTHR) {
        int j = idx / RPS_, rr = idx % RPS_;
        ws[j][rr] = w[j * N_DIM + r0 + rr];
    }
    __syncthreads();

    u64 acc[JD][2];
    #pragma unroll
    for (int j = 0; j < JD; j++) { acc[j][0] = 0ull; acc[j][1] = 0ull; }

    const ulonglong2* bp = (const ulonglong2*)big + (((size_t)r0 * N_DIM + c0) >> 2);
    #pragma unroll 8
    for (int rr = 0; rr < RPS_; rr++) {
        ulonglong2 d = bp[(size_t)rr * (N_DIM / 4)];
        #pragma unroll
        for (int j = 0; j < JD; j++) {
            u64 wp = pk2(ws[j][rr], ws[j][rr]);
            fma2(acc[j][0], d.x, wp);
            fma2(acc[j][1], d.y, wp);
        }
    }

    #pragma unroll
    for (int j = 0; j < JD; j++) {
        float2 a = upk(acc[j][0]), b = upk(acc[j][1]);
        red4(out + j * N_DIM + c0, a.x, a.y, b.x, b.y);
    }
}

__device__ __forceinline__ void rowgemv_body(const float* __restrict__ big,
                                             const float* __restrict__ S,
                                             float* __restrict__ partbase,
                                             int rowblk, int ks,
                                             ulonglong2 (*ss)[CPK / 4]) {
    const int tid = threadIdx.x;
    const int wid = tid >> 5;
    const int lane = tid & 31;
    const int cbase = ks * CPK;
    const int r0 = rowblk * RGROWS + wid * 2;

    for (int idx = tid; idx < JD * (CPK / 4); idx += NTHR) {
        int j = idx >> 7, q = idx & 127;
        ss[j][q] = ((const ulonglong2*)(S + j * N_DIM + cbase))[q];
    }
    __syncthreads();

    u64 a0[JD], a1[JD];
    #pragma unroll
    for (int j = 0; j < JD; j++) { a0[j] = 0ull; a1[j] = 0ull; }

    const ulonglong2* b0 = (const ulonglong2*)(big + (size_t)r0 * N_DIM + cbase);
    const ulonglong2* b1 = (const ulonglong2*)(big + (size_t)(r0 + 1) * N_DIM + cbase);

    #pragma unroll
    for (int it = 0; it < CPK / 128; it++) {     // 4 iterations
        const int q = it * 32 + lane;
        ulonglong2 m0 = b0[q], m1 = b1[q];
        #pragma unroll
        for (int j = 0; j < JD; j++) {
            ulonglong2 sv = ss[j][q];
            fma2(a0[j], m0.x, sv.x); fma2(a0[j], m0.y, sv.y);
            fma2(a1[j], m1.x, sv.x); fma2(a1[j], m1.y, sv.y);
        }
    }

    #pragma unroll
    for (int j = 0; j < JD; j++) {
        #pragma unroll
        for (int o = 16; o; o >>= 1) {
            add2(a0[j], __shfl_xor_sync(0xffffffffu, a0[j], o));
            add2(a1[j], __shfl_xor_sync(0xffffffffu, a1[j], o));
        }
    }

    if (lane == 0) {
        float* p = partbase + (size_t)ks * (N_DIM * JD);
        #pragma unroll
        for (int j = 0; j < JD; j++) {
            float2 f0 = upk(a0[j]), f1 = upk(a1[j]);
            p[(size_t)r0 * JD + j] = f0.x + f0.y;
            p[(size_t)(r0 + 1) * JD + j] = f1.x + f1.y;
        }
    }
}

// --------------------------------------------------------------------------
// Phase 1: T-splitk (red.v4 into g_T) + k-rowgemv (slot0) + slin.
// --------------------------------------------------------------------------
__global__ void __launch_bounds__(NTHR) phase1_kernel(
        const float* __restrict__ data_q, const float* __restrict__ W_lin,
        const float* __restrict__ W_k,    const float* __restrict__ data_k) {
    __shared__ ulonglong2 ss[JD][CPK / 4];   // 12KB (splitk aliases as ws)
    const int bid = blockIdx.x;
    if (bid < SPLITK_T_BLOCKS) {
        splitk_body<RPS_T>(data_q, W_lin, g_T, bid & 3, bid >> 2, (float (*)[RPS_T])ss);
    } else if (bid < SPLITK_T_BLOCKS + RG_BLOCKS) {
        const int rb = bid - SPLITK_T_BLOCKS;
        rowgemv_body(W_k, data_k, g_rgpart, rb >> 3, rb & 7, ss);
    } else {
        slin_body(W_lin);
    }
}

// --------------------------------------------------------------------------
// Phase 2: fused nq -> kmod -> v over ONE DRAM streaming of W_q (sweep C hits
// L2). 128 blocks x 512 threads, 32 rows/block, 8 cols/thread.
// Packed over (j, j+1) pairs: lanes of u64 = j parity.
// --------------------------------------------------------------------------
__global__ void __launch_bounds__(512) phase2_kernel(
        const float* __restrict__ Wq,  const float* __restrict__ b_q,
        const float* __restrict__ b_k, const float* __restrict__ b_lin) {
    __shared__ float nqw[16][P2_ROWS][JD];   // [warp][row][j], 12KB
    __shared__ float kmod_s[P2_ROWS][JD];

    const int tid = threadIdx.x;
    const int w = tid >> 5;
    const int lane = tid & 31;
    const int r0 = blockIdx.x * P2_ROWS;
    const int cu = tid * 2;                  // ulonglong2 index (8 cols/thread)

    // T chunk packed by j-pairs: Tp[p][c] = (T[2p][col], T[2p+1][col])
    u64 Tp[3][8];
    #pragma unroll
    for (int p = 0; p < 3; p++) {
        const float4* e4 = (const float4*)(g_T + (2 * p) * N_DIM);
        const float4* o4 = (const float4*)(g_T + (2 * p + 1) * N_DIM);
        float4 e0 = e4[tid * 2], e1 = e4[tid * 2 + 1];
        float4 o0 = o4[tid * 2], o1 = o4[tid * 2 + 1];
        Tp[p][0] = pk2(e0.x, o0.x); Tp[p][1] = pk2(e0.y, o0.y);
        Tp[p][2] = pk2(e0.z, o0.z); Tp[p][3] = pk2(e0.w, o0.w);
        Tp[p][4] = pk2(e1.x, o1.x); Tp[p][5] = pk2(e1.y, o1.y);
        Tp[p][6] = pk2(e1.z, o1.z); Tp[p][7] = pk2(e1.w, o1.w);
    }

    // ---- Sweep A: nq partial dots (streams the block's 32 rows of W_q) ----
    const ulonglong2* wrow = (const ulonglong2*)(Wq + (size_t)r0 * N_DIM) + cu;
    #pragma unroll 2
    for (int rr = 0; rr < P2_ROWS; rr++) {
        ulonglong2 m0 = wrow[0], m1 = wrow[1];
        wrow += N_DIM / 4;
        float2 f0 = upk(m0.x), f1 = upk(m0.y), f2 = upk(m1.x), f3 = upk(m1.y);
        u64 mm[8];
        mm[0] = pk2(f0.x, f0.x); mm[1] = pk2(f0.y, f0.y);
        mm[2] = pk2(f1.x, f1.x); mm[3] = pk2(f1.y, f1.y);
        mm[4] = pk2(f2.x, f2.x); mm[5] = pk2(f2.y, f2.y);
        mm[6] = pk2(f3.x, f3.x); mm[7] = pk2(f3.y, f3.y);

        u64 acc[3] = {0ull, 0ull, 0ull};
        #pragma unroll
        for (int p = 0; p < 3; p++)
            #pragma unroll
            for (int c = 0; c < 8; c++)
                fma2(acc[p], mm[c], Tp[p][c]);

        #pragma unroll
        for (int p = 0; p < 3; p++) {
            #pragma unroll
            for (int o = 16; o; o >>= 1)
                add2(acc[p], __shfl_xor_sync(0xffffffffu, acc[p], o));
        }
        if (lane == 0) {
            #pragma unroll
            for (int p = 0; p < 3; p++) {
                float2 f = upk(acc[p]);
                nqw[w][rr][2 * p] = f.x;
                nqw[w][rr][2 * p + 1] = f.y;
            }
        }
    }
    __syncthreads();

    // ---- Phase B: finalize k (from phase1 partials), nq -> kmod ----
    if (tid < P2_ROWS * JD) {
        const int rr = tid & 31;
        const int j = tid >> 5;
        const int m = r0 + rr;
        float nq = 0.f;
        #pragma unroll
        for (int ww = 0; ww < 16; ww++) nq += nqw[ww][rr][j];
        nq += b_q[m] * g_slin[j] + b_lin[j];
        float kv = 0.f;
        #pragma unroll
        for (int ks = 0; ks < KSPLIT; ks++)
            kv += g_rgpart[((size_t)ks * N_DIM + m) * JD + j];
        kv += b_k[m];
        float x = fmaf(kv, kv, 2.0f * kv) + nq * (1.0f + fabsf(kv));
        kmod_s[rr][j] = fminf(fmaxf(x, 0.0f), 6.0f);
    }
    __syncthreads();

    // ---- Sweep C: v accumulation (re-reads the same 32 rows; L2-resident) ----
    u64 vp[3][8];
    #pragma unroll
    for (int p = 0; p < 3; p++)
        #pragma unroll
        for (int c = 0; c < 8; c++) vp[p][c] = 0ull;

    wrow = (const ulonglong2*)(Wq + (size_t)r0 * N_DIM) + cu;
    #pragma unroll 2
    for (int rr = 0; rr < P2_ROWS; rr++) {
        ulonglong2 m0 = wrow[0], m1 = wrow[1];
        wrow += N_DIM / 4;
        float2 f0 = upk(m0.x), f1 = upk(m0.y), f2 = upk(m1.x), f3 = upk(m1.y);
        u64 mm[8];
        mm[0] = pk2(f0.x, f0.x); mm[1] = pk2(f0.y, f0.y);
        mm[2] = pk2(f1.x, f1.x); mm[3] = pk2(f1.y, f1.y);
        mm[4] = pk2(f2.x, f2.x); mm[5] = pk2(f2.y, f2.y);
        mm[6] = pk2(f3.x, f3.x); mm[7] = pk2(f3.y, f3.y);

        u64 km[3];
        #pragma unroll
        for (int p = 0; p < 3; p++) km[p] = pk2(kmod_s[rr][2 * p], kmod_s[rr][2 * p + 1]);

        #pragma unroll
        for (int p = 0; p < 3; p++)
            #pragma unroll
            for (int c = 0; c < 8; c++)
                fma2(vp[p][c], mm[c], km[p]);
    }

    // atomically accumulate v: thread owns cols c0..c0+7 for all 6 j
    const int c0 = tid * 8;
    #pragma unroll
    for (int p = 0; p < 3; p++) {
        float2 u0 = upk(vp[p][0]), u1 = upk(vp[p][1]), u2 = upk(vp[p][2]), u3 = upk(vp[p][3]);
        float2 u4 = upk(vp[p][4]), u5 = upk(vp[p][5]), u6 = upk(vp[p][6]), u7 = upk(vp[p][7]);
        float* ev = g_v + (2 * p) * N_DIM + c0;
        float* ov = g_v + (2 * p + 1) * N_DIM + c0;
        red4(ev + 0, u0.x, u1.x, u2.x, u3.x);
        red4(ev + 4, u4.x, u5.x, u6.x, u7.x);
        red4(ov + 0, u0.y, u1.y, u2.y, u3.y);
        red4(ov + 4, u4.y, u5.y, u6.y, u7.y);
    }

    // c partials: c[j] = sum_rr b_q[r0+rr] * kmod[rr][j]
    if (tid < JD) {
        float s = 0.f;
        #pragma unroll
        for (int rr = 0; rr < P2_ROWS; rr++)
            s += b_q[r0 + rr] * kmod_s[rr][tid];
        g_cpart[blockIdx.x * JD + tid] = s;
    }
}

// dot pass: data_q x g_v -> slot0 partials (k partials consumed by phase2)
__global__ void __launch_bounds__(NTHR) dot_kernel(const float* __restrict__ data_q) {
    __shared__ ulonglong2 ss[JD][CPK / 4];
    rowgemv_body(data_q, g_v, g_rgpart, blockIdx.x, blockIdx.y, ss);
}

// --------------------------------------------------------------------------
// Epilogue B: c[j] = sum_b g_cpart[b][j]; out[m,j] = (dotpart-sum + c[j]) / 64.
// Tail: re-zero g_T and g_v for the next call (graph replays).
// --------------------------------------------------------------------------
__global__ void __launch_bounds__(128) epilogueB_kernel(float* __restrict__ out) {
    const int tid = threadIdx.x;
    const int m = blockIdx.x * 128 + tid;

    float acc[JD];
    #pragma unroll
    for (int j = 0; j < JD; j++) acc[j] = 0.f;
    #pragma unroll 4
    for (int b = 0; b < P2_BLOCKS; b++)
        #pragma unroll
        for (int j = 0; j < JD; j++) acc[j] += g_cpart[b * JD + j];

    #pragma unroll
    for (int ks = 0; ks < KSPLIT; ks++) {
        const float* p = g_rgpart + ((size_t)ks * N_DIM + m) * JD;
        #pragma unroll
        for (int j = 0; j < JD; j++) acc[j] += p[j];
    }
    #pragma unroll
    for (int j = 0; j < JD; j++)
        out[m * JD + j] = acc[j] * 0.015625f;

    // tail-zero accumulators for the next invocation
    const int gt = blockIdx.x * 128 + tid;               // 4096 threads
    float4* t4 = (float4*)g_T;
    float4* v4 = (float4*)g_v;
    const float4 z = make_float4(0.f, 0.f, 0.f, 0.f);
    #pragma unroll
    for (int idx = gt; idx < JD * N_DIM / 4; idx += EPIB_BLOCKS * 128) {
        t4[idx] = z;
        v4[idx] = z;
    }
}

// --------------------------------------------------------------------------
extern "C" void kernel_launch(void* const* d_in, const int* in_sizes, int n_in,
                              void* d_out, int out_size) {
    const float* data_q = (const float*)d_in[0];   // [4096,4096]
    const float* data_k = (const float*)d_in[1];   // [6,4096]
    const float* W_q    = (const float*)d_in[2];   // [4096,4096]
    const float* b_q    = (const float*)d_in[3];   // [4096]
    const float* W_lin  = (const float*)d_in[4];   // [6,4096]
    const float* b_lin  = (const float*)d_in[5];   // [6]
    const float* W_k    = (const float*)d_in[6];   // [4096,4096]
    const float* b_k    = (const float*)d_in[7];   // [4096]
    float* out = (float*)d_out;                    // [4096,6]

    phase1_kernel<<<SPLITK_T_BLOCKS + RG_BLOCKS + 1, NTHR>>>(data_q, W_lin, W_k, data_k);
    phase2_kernel<<<P2_BLOCKS, 512>>>(W_q, b_q, b_k, b_lin);     // nq+kmod+v+c, W_q once
    dot_kernel<<<dim3(RGX, KSPLIT), NTHR>>>(data_q);             // dot partials
    epilogueB_kernel<<<EPIB_BLOCKS, 128>>>(out);                 // out + re-zero
}

// round 15
// speedup vs baseline: 1.1114x; 1.1114x over previous
#include <cuda_runtime.h>

// ---------------------------------------------------------------------------
// CMIAttentionMatrixForAcrobot, restructured:
//   T[j,i]   = sum_n data_q[n,i] * W_lin[j,n]            (phase1 splitk -> red.v4 g_T)
//   k[j,m]   = sum_i data_k[j,i] * W_k[m,i] + b_k[m]     (phase1 rowgemv, slot0)
//   nq[m,j]  = sum_i W_q[m,i] * T[j,i] + b_q[m]*slin[j] + b_lin[j]   (phase2 A)
//   kmod     = relu6(k^2 + 2k + nq*(1+|k|))              (phase2 B)
//   v[j,i]   = sum_m W_q[m,i] * kmod[j,m]                (phase2 C -> red.v4 g_v;
//                                                         W_q re-read hits L2)
//   c[j]     = sum_m b_q[m] * kmod[j,m]                  (phase2 partials)
//   out[n,j] = (sum_i data_q[n,i] * v[j,i] + c[j]) / 64  (dot rowgemv + epi B)
// phase2 reads W_q from DRAM ONCE (sweep C re-reads from L2: 128 concurrent
// blocks x 512KB = full 64MB W_q < 126MB L2). EpilogueB's c-reduction is
// parallel (one cpart row per thread + smem tree), not a serial scan.
// g_T/g_v zero-invariant maintained by epilogueB's tail. 4 launches + epilogue.
// ---------------------------------------------------------------------------

typedef unsigned long long u64;

#define N_DIM 4096
#define JD 6
#define NTHR 256

// T splitk: 64 rows x 1024 cols per block
#define RPS_T 64
#define NSPLIT_T 64
#define SPLITK_T_BLOCKS (4 * NSPLIT_T)    // 256

// row-GEMV: 16 rows (8 warps x 2 rows) x 512 cols per block
#define KSPLIT 8
#define CPK (N_DIM / KSPLIT)              // 512
#define RGROWS 16
#define RGX (N_DIM / RGROWS)              // 256
#define RG_BLOCKS (RGX * KSPLIT)          // 2048

// phase2: 128 blocks x 512 threads x 32 rows
#define P2_BLOCKS 128
#define P2_ROWS 32

#define EPIB_BLOCKS 32

// scratch (static device globals; zero-initialized at module load)
__device__ float g_T[JD * N_DIM];
__device__ float g_v[JD * N_DIM];
__device__ float g_rgpart[2 * KSPLIT * N_DIM * JD];   // slot0: k then dot
__device__ float g_cpart[P2_BLOCKS * JD];
__device__ float g_slin[JD];

// ---- packed fp32x2 helpers ------------------------------------------------
__device__ __forceinline__ u64 pk2(float a, float b) {
    u64 r;
    asm("mov.b64 %0, {%1, %2};" : "=l"(r) : "r"(__float_as_uint(a)), "r"(__float_as_uint(b)));
    return r;
}
__device__ __forceinline__ float2 upk(u64 v) {
    unsigned lo, hi;
    asm("mov.b64 {%0, %1}, %2;" : "=r"(lo), "=r"(hi) : "l"(v));
    return make_float2(__uint_as_float(lo), __uint_as_float(hi));
}
__device__ __forceinline__ void fma2(u64& d, u64 a, u64 b) {
    asm("fma.rn.f32x2 %0, %1, %2, %0;" : "+l"(d) : "l"(a), "l"(b));
}
__device__ __forceinline__ void add2(u64& d, u64 a) {
    asm("add.rn.f32x2 %0, %0, %1;" : "+l"(d) : "l"(a));
}
// vectored global float reduction (sm_90+), 4 floats per op
__device__ __forceinline__ void red4(float* gp, float a, float b, float c, float d) {
    asm volatile(
        "{\n\t.reg .u64 p;\n\t"
        "cvta.to.global.u64 p, %0;\n\t"
        "red.global.add.v4.f32 [p], {%1, %2, %3, %4};\n\t}"
        :: "l"(gp), "f"(a), "f"(b), "f"(c), "f"(d) : "memory");
}

// --------------------------------------------------------------------------
// phase-1 bodies (256-thread blocks)
// --------------------------------------------------------------------------
__device__ __forceinline__ void slin_body(const float* __restrict__ Wlin) {
    const int wid = threadIdx.x >> 5;
    const int lane = threadIdx.x & 31;
    if (wid < JD) {
        const float4* p = (const float4*)(Wlin + wid * N_DIM);
        float s = 0.0f;
        for (int q = lane; q < N_DIM / 4; q += 32) {
            float4 v = p[q];
            s += v.x + v.y + v.z + v.w;
        }
        #pragma unroll
        for (int o = 16; o; o >>= 1) s += __shfl_xor_sync(0xffffffffu, s, o);
        if (lane == 0) g_slin[wid] = s;
    }
}

template<int RPS_>
__device__ __forceinline__ void splitk_body(const float* __restrict__ big,
                                            const float* __restrict__ w,
                                            float* __restrict__ out,
                                            int cslab, int split,
                                            float (*ws)[RPS_]) {
    const int tid = threadIdx.x;
    const int c0 = cslab * 1024 + tid * 4;
    const int r0 = split * RPS_;

    for (int idx = tid; idx < JD * RPS_; idx += NTHR) {
        int j = idx / RPS_, rr = idx % RPS_;
        ws[j][rr] = w[j * N_DIM + r0 + rr];
    }
    __syncthreads();

    u64 acc[JD][2];
    #pragma unroll
    for (int j = 0; j < JD; j++) { acc[j][0] = 0ull; acc[j][1] = 0ull; }

    const ulonglong2* bp = (const ulonglong2*)big + (((size_t)r0 * N_DIM + c0) >> 2);
    #pragma unroll 8
    for (int rr = 0; rr < RPS_; rr++) {
        ulonglong2 d = bp[(size_t)rr * (N_DIM / 4)];
        #pragma unroll
        for (int j = 0; j < JD; j++) {
            u64 wp = pk2(ws[j][rr], ws[j][rr]);
            fma2(acc[j][0], d.x, wp);
            fma2(acc[j][1], d.y, wp);
        }
    }

    #pragma unroll
    for (int j = 0; j < JD; j++) {
        float2 a = upk(acc[j][0]), b = upk(acc[j][1]);
        red4(out + j * N_DIM + c0, a.x, a.y, b.x, b.y);
    }
}

__device__ __forceinline__ void rowgemv_body(const float* __restrict__ big,
                                             const float* __restrict__ S,
                                             float* __restrict__ partbase,
                                             int rowblk, int ks,
                                             ulonglong2 (*ss)[CPK / 4]) {
    const int tid = threadIdx.x;
    const int wid = tid >> 5;
    const int lane = tid & 31;
    const int cbase = ks * CPK;
    const int r0 = rowblk * RGROWS + wid * 2;

    for (int idx = tid; idx < JD * (CPK / 4); idx += NTHR) {
        int j = idx >> 7, q = idx & 127;
        ss[j][q] = ((const ulonglong2*)(S + j * N_DIM + cbase))[q];
    }
    __syncthreads();

    u64 a0[JD], a1[JD];
    #pragma unroll
    for (int j = 0; j < JD; j++) { a0[j] = 0ull; a1[j] = 0ull; }

    const ulonglong2* b0 = (const ulonglong2*)(big + (size_t)r0 * N_DIM + cbase);
    const ulonglong2* b1 = (const ulonglong2*)(big + (size_t)(r0 + 1) * N_DIM + cbase);

    #pragma unroll
    for (int it = 0; it < CPK / 128; it++) {     // 4 iterations
        const int q = it * 32 + lane;
        ulonglong2 m0 = b0[q], m1 = b1[q];
        #pragma unroll
        for (int j = 0; j < JD; j++) {
            ulonglong2 sv = ss[j][q];
            fma2(a0[j], m0.x, sv.x); fma2(a0[j], m0.y, sv.y);
            fma2(a1[j], m1.x, sv.x); fma2(a1[j], m1.y, sv.y);
        }
    }

    #pragma unroll
    for (int j = 0; j < JD; j++) {
        #pragma unroll
        for (int o = 16; o; o >>= 1) {
            add2(a0[j], __shfl_xor_sync(0xffffffffu, a0[j], o));
            add2(a1[j], __shfl_xor_sync(0xffffffffu, a1[j], o));
        }
    }

    if (lane == 0) {
        float* p = partbase + (size_t)ks * (N_DIM * JD);
        #pragma unroll
        for (int j = 0; j < JD; j++) {
            float2 f0 = upk(a0[j]), f1 = upk(a1[j]);
            p[(size_t)r0 * JD + j] = f0.x + f0.y;
            p[(size_t)(r0 + 1) * JD + j] = f1.x + f1.y;
        }
    }
}

// --------------------------------------------------------------------------
// Phase 1: T-splitk (red.v4 into g_T) + k-rowgemv (slot0) + slin.
// --------------------------------------------------------------------------
__global__ void __launch_bounds__(NTHR) phase1_kernel(
        const float* __restrict__ data_q, const float* __restrict__ W_lin,
        const float* __restrict__ W_k,    const float* __restrict__ data_k) {
    __shared__ ulonglong2 ss[JD][CPK / 4];   // 12KB (splitk aliases as ws)
    const int bid = blockIdx.x;
    if (bid < SPLITK_T_BLOCKS) {
        splitk_body<RPS_T>(data_q, W_lin, g_T, bid & 3, bid >> 2, (float (*)[RPS_T])ss);
    } else if (bid < SPLITK_T_BLOCKS + RG_BLOCKS) {
        const int rb = bid - SPLITK_T_BLOCKS;
        rowgemv_body(W_k, data_k, g_rgpart, rb >> 3, rb & 7, ss);
    } else {
        slin_body(W_lin);
    }
}

// --------------------------------------------------------------------------
// Phase 2: fused nq -> kmod -> v over ONE DRAM streaming of W_q (sweep C hits
// L2). 128 blocks x 512 threads, 32 rows/block, 8 cols/thread.
// Packed over (j, j+1) pairs: lanes of u64 = j parity.
// --------------------------------------------------------------------------
__global__ void __launch_bounds__(512) phase2_kernel(
        const float* __restrict__ Wq,  const float* __restrict__ b_q,
        const float* __restrict__ b_k, const float* __restrict__ b_lin) {
    __shared__ float nqw[16][P2_ROWS][JD];   // [warp][row][j], 12KB
    __shared__ float kmod_s[P2_ROWS][JD];

    const int tid = threadIdx.x;
    const int w = tid >> 5;
    const int lane = tid & 31;
    const int r0 = blockIdx.x * P2_ROWS;
    const int cu = tid * 2;                  // ulonglong2 index (8 cols/thread)

    // T chunk packed by j-pairs: Tp[p][c] = (T[2p][col], T[2p+1][col])
    u64 Tp[3][8];
    #pragma unroll
    for (int p = 0; p < 3; p++) {
        const float4* e4 = (const float4*)(g_T + (2 * p) * N_DIM);
        const float4* o4 = (const float4*)(g_T + (2 * p + 1) * N_DIM);
        float4 e0 = e4[tid * 2], e1 = e4[tid * 2 + 1];
        float4 o0 = o4[tid * 2], o1 = o4[tid * 2 + 1];
        Tp[p][0] = pk2(e0.x, o0.x); Tp[p][1] = pk2(e0.y, o0.y);
        Tp[p][2] = pk2(e0.z, o0.z); Tp[p][3] = pk2(e0.w, o0.w);
        Tp[p][4] = pk2(e1.x, o1.x); Tp[p][5] = pk2(e1.y, o1.y);
        Tp[p][6] = pk2(e1.z, o1.z); Tp[p][7] = pk2(e1.w, o1.w);
    }

    // ---- Sweep A: nq partial dots (streams the block's 32 rows of W_q) ----
    const ulonglong2* wrow = (const ulonglong2*)(Wq + (size_t)r0 * N_DIM) + cu;
    #pragma unroll 2
    for (int rr = 0; rr < P2_ROWS; rr++) {
        ulonglong2 m0 = wrow[0], m1 = wrow[1];
        wrow += N_DIM / 4;
        float2 f0 = upk(m0.x), f1 = upk(m0.y), f2 = upk(m1.x), f3 = upk(m1.y);
        u64 mm[8];
        mm[0] = pk2(f0.x, f0.x); mm[1] = pk2(f0.y, f0.y);
        mm[2] = pk2(f1.x, f1.x); mm[3] = pk2(f1.y, f1.y);
        mm[4] = pk2(f2.x, f2.x); mm[5] = pk2(f2.y, f2.y);
        mm[6] = pk2(f3.x, f3.x); mm[7] = pk2(f3.y, f3.y);

        u64 acc[3] = {0ull, 0ull, 0ull};
        #pragma unroll
        for (int p = 0; p < 3; p++)
            #pragma unroll
            for (int c = 0; c < 8; c++)
                fma2(acc[p], mm[c], Tp[p][c]);

        #pragma unroll
        for (int p = 0; p < 3; p++) {
            #pragma unroll
            for (int o = 16; o; o >>= 1)
                add2(acc[p], __shfl_xor_sync(0xffffffffu, acc[p], o));
        }
        if (lane == 0) {
            #pragma unroll
            for (int p = 0; p < 3; p++) {
                float2 f = upk(acc[p]);
                nqw[w][rr][2 * p] = f.x;
                nqw[w][rr][2 * p + 1] = f.y;
            }
        }
    }
    __syncthreads();

    // ---- Phase B: finalize k (from phase1 partials), nq -> kmod ----
    if (tid < P2_ROWS * JD) {
        const int rr = tid & 31;
        const int j = tid >> 5;
        const int m = r0 + rr;
        float nq = 0.f;
        #pragma unroll
        for (int ww = 0; ww < 16; ww++) nq += nqw[ww][rr][j];
        nq += b_q[m] * g_slin[j] + b_lin[j];
        float kv = 0.f;
        #pragma unroll
        for (int ks = 0; ks < KSPLIT; ks++)
            kv += g_rgpart[((size_t)ks * N_DIM + m) * JD + j];
        kv += b_k[m];
        float x = fmaf(kv, kv, 2.0f * kv) + nq * (1.0f + fabsf(kv));
        kmod_s[rr][j] = fminf(fmaxf(x, 0.0f), 6.0f);
    }
    __syncthreads();

    // ---- Sweep C: v accumulation (re-reads the same 32 rows; L2-resident) ----
    u64 vp[3][8];
    #pragma unroll
    for (int p = 0; p < 3; p++)
        #pragma unroll
        for (int c = 0; c < 8; c++) vp[p][c] = 0ull;

    wrow = (const ulonglong2*)(Wq + (size_t)r0 * N_DIM) + cu;
    #pragma unroll 2
    for (int rr = 0; rr < P2_ROWS; rr++) {
        ulonglong2 m0 = wrow[0], m1 = wrow[1];
        wrow += N_DIM / 4;
        float2 f0 = upk(m0.x), f1 = upk(m0.y), f2 = upk(m1.x), f3 = upk(m1.y);
        u64 mm[8];
        mm[0] = pk2(f0.x, f0.x); mm[1] = pk2(f0.y, f0.y);
        mm[2] = pk2(f1.x, f1.x); mm[3] = pk2(f1.y, f1.y);
        mm[4] = pk2(f2.x, f2.x); mm[5] = pk2(f2.y, f2.y);
        mm[6] = pk2(f3.x, f3.x); mm[7] = pk2(f3.y, f3.y);

        u64 km[3];
        #pragma unroll
        for (int p = 0; p < 3; p++) km[p] = pk2(kmod_s[rr][2 * p], kmod_s[rr][2 * p + 1]);

        #pragma unroll
        for (int p = 0; p < 3; p++)
            #pragma unroll
            for (int c = 0; c < 8; c++)
                fma2(vp[p][c], mm[c], km[p]);
    }

    // atomically accumulate v: thread owns cols c0..c0+7 for all 6 j
    const int c0 = tid * 8;
    #pragma unroll
    for (int p = 0; p < 3; p++) {
        float2 u0 = upk(vp[p][0]), u1 = upk(vp[p][1]), u2 = upk(vp[p][2]), u3 = upk(vp[p][3]);
        float2 u4 = upk(vp[p][4]), u5 = upk(vp[p][5]), u6 = upk(vp[p][6]), u7 = upk(vp[p][7]);
        float* ev = g_v + (2 * p) * N_DIM + c0;
        float* ov = g_v + (2 * p + 1) * N_DIM + c0;
        red4(ev + 0, u0.x, u1.x, u2.x, u3.x);
        red4(ev + 4, u4.x, u5.x, u6.x, u7.x);
        red4(ov + 0, u0.y, u1.y, u2.y, u3.y);
        red4(ov + 4, u4.y, u5.y, u6.y, u7.y);
    }

    // c partials: c[j] = sum_rr b_q[r0+rr] * kmod[rr][j]
    if (tid < JD) {
        float s = 0.f;
        #pragma unroll
        for (int rr = 0; rr < P2_ROWS; rr++)
            s += b_q[r0 + rr] * kmod_s[rr][tid];
        g_cpart[blockIdx.x * JD + tid] = s;
    }
}

// dot pass: data_q x g_v -> slot0 partials (k partials consumed by phase2)
__global__ void __launch_bounds__(NTHR) dot_kernel(const float* __restrict__ data_q) {
    __shared__ ulonglong2 ss[JD][CPK / 4];
    rowgemv_body(data_q, g_v, g_rgpart, blockIdx.x, blockIdx.y, ss);
}

// --------------------------------------------------------------------------
// Epilogue B: PARALLEL c-reduction (thread t loads cpart row t, smem tree),
// then out[m,j] = (dotpart-sum + c[j]) / 64.
// Tail: re-zero g_T and g_v for the next call (graph replays).
// --------------------------------------------------------------------------
__global__ void __launch_bounds__(128) epilogueB_kernel(float* __restrict__ out) {
    __shared__ float red[128][JD];
    __shared__ float cs[JD];
    const int tid = threadIdx.x;

    // parallel load: thread tid owns cpart row tid (P2_BLOCKS == 128)
    {
        const float* cp = g_cpart + tid * JD;
        #pragma unroll
        for (int j = 0; j < JD; j++) red[tid][j] = cp[j];
    }
    __syncthreads();
    for (int s = 64; s > 0; s >>= 1) {
        if (tid < s) {
            #pragma unroll
            for (int j = 0; j < JD; j++) red[tid][j] += red[tid + s][j];
        }
        __syncthreads();
    }
    if (tid < JD) cs[tid] = red[0][tid];
    __syncthreads();

    const int m = blockIdx.x * 128 + tid;
    float acc[JD];
    #pragma unroll
    for (int j = 0; j < JD; j++) acc[j] = cs[j];
    #pragma unroll
    for (int ks = 0; ks < KSPLIT; ks++) {
        const float* p = g_rgpart + ((size_t)ks * N_DIM + m) * JD;
        #pragma unroll
        for (int j = 0; j < JD; j++) acc[j] += p[j];
    }
    #pragma unroll
    for (int j = 0; j < JD; j++)
        out[m * JD + j] = acc[j] * 0.015625f;

    // tail-zero accumulators for the next invocation
    const int gt = blockIdx.x * 128 + tid;               // 4096 threads
    float4* t4 = (float4*)g_T;
    float4* v4 = (float4*)g_v;
    const float4 z = make_float4(0.f, 0.f, 0.f, 0.f);
    #pragma unroll
    for (int idx = gt; idx < JD * N_DIM / 4; idx += EPIB_BLOCKS * 128) {
        t4[idx] = z;
        v4[idx] = z;
    }
}

// --------------------------------------------------------------------------
extern "C" void kernel_launch(void* const* d_in, const int* in_sizes, int n_in,
                              void* d_out, int out_size) {
    const float* data_q = (const float*)d_in[0];   // [4096,4096]
    const float* data_k = (const float*)d_in[1];   // [6,4096]
    const float* W_q    = (const float*)d_in[2];   // [4096,4096]
    const float* b_q    = (const float*)d_in[3];   // [4096]
    const float* W_lin  = (const float*)d_in[4];   // [6,4096]
    const float* b_lin  = (const float*)d_in[5];   // [6]
    const float* W_k    = (const float*)d_in[6];   // [4096,4096]
    const float* b_k    = (const float*)d_in[7];   // [4096]
    float* out = (float*)d_out;                    // [4096,6]

    phase1_kernel<<<SPLITK_T_BLOCKS + RG_BLOCKS + 1, NTHR>>>(data_q, W_lin, W_k, data_k);
    phase2_kernel<<<P2_BLOCKS, 512>>>(W_q, b_q, b_k, b_lin);     // nq+kmod+v+c, W_q once
    dot_kernel<<<dim3(RGX, KSPLIT), NTHR>>>(data_q);             // dot partials
    epilogueB_kernel<<<EPIB_BLOCKS, 128>>>(out);                 // out + re-zero
}

// round 16
// speedup vs baseline: 1.1542x; 1.0386x over previous
#include <cuda_runtime.h>

// ---------------------------------------------------------------------------
// CMIAttentionMatrixForAcrobot, restructured:
//   T[j,i]   = sum_n data_q[n,i] * W_lin[j,n]            (phase1 splitk -> red.v4 g_T)
//   k[j,m]   = sum_i data_k[j,i] * W_k[m,i] + b_k[m]     (phase1 rowgemv, slot0)
//   nq[m,j]  = sum_i W_q[m,i] * T[j,i] + b_q[m]*slin[j] + b_lin[j]   (phase2 A)
//   kmod     = relu6(k^2 + 2k + nq*(1+|k|))              (phase2 B)
//   v[j,i]   = sum_m W_q[m,i] * kmod[j,m]                (phase2 C -> red.v4 g_v;
//                                                         W_q re-read hits L2)
//   c[j]     = sum_m b_q[m] * kmod[j,m]                  (phase2 partials)
//   out[n,j] = (sum_i data_q[n,i] * v[j,i] + c[j]) / 64
//              (init_out writes c/64; dot reds scaled partials straight into out)
// Zero-invariants across graph replays: g_T zeroed by init_out (after phase2
// consumed it); g_v zeroed by phase1's tail block (before phase2's reds,
// after the previous call's dot consumed it). 4 launches.
// ---------------------------------------------------------------------------

typedef unsigned long long u64;

#define N_DIM 4096
#define JD 6
#define NTHR 256

// T splitk: 64 rows x 1024 cols per block
#define RPS_T 64
#define NSPLIT_T 64
#define SPLITK_T_BLOCKS (4 * NSPLIT_T)    // 256

// row-GEMV: 16 rows (8 warps x 2 rows) x 512 cols per block
#define KSPLIT 8
#define CPK (N_DIM / KSPLIT)              // 512
#define RGROWS 16
#define RGX (N_DIM / RGROWS)              // 256
#define RG_BLOCKS (RGX * KSPLIT)          // 2048

// phase2: 128 blocks x 512 threads x 32 rows
#define P2_BLOCKS 128
#define P2_ROWS 32

#define OUT_SCALE 0.015625f               // 1/64

// scratch (static device globals; zero-initialized at module load)
__device__ float g_T[JD * N_DIM];
__device__ float g_v[JD * N_DIM];
__device__ float g_rgpart[KSPLIT * N_DIM * JD];   // k partials (phase1 -> phase2)
__device__ float g_cpart[P2_BLOCKS * JD];
__device__ float g_slin[JD];

// ---- packed fp32x2 helpers ------------------------------------------------
__device__ __forceinline__ u64 pk2(float a, float b) {
    u64 r;
    asm("mov.b64 %0, {%1, %2};" : "=l"(r) : "r"(__float_as_uint(a)), "r"(__float_as_uint(b)));
    return r;
}
__device__ __forceinline__ float2 upk(u64 v) {
    unsigned lo, hi;
    asm("mov.b64 {%0, %1}, %2;" : "=r"(lo), "=r"(hi) : "l"(v));
    return make_float2(__uint_as_float(lo), __uint_as_float(hi));
}
__device__ __forceinline__ void fma2(u64& d, u64 a, u64 b) {
    asm("fma.rn.f32x2 %0, %1, %2, %0;" : "+l"(d) : "l"(a), "l"(b));
}
__device__ __forceinline__ void add2(u64& d, u64 a) {
    asm("add.rn.f32x2 %0, %0, %1;" : "+l"(d) : "l"(a));
}
// vectored global float reductions (sm_90+)
__device__ __forceinline__ void red4(float* gp, float a, float b, float c, float d) {
    asm volatile(
        "{\n\t.reg .u64 p;\n\t"
        "cvta.to.global.u64 p, %0;\n\t"
        "red.global.add.v4.f32 [p], {%1, %2, %3, %4};\n\t}"
        :: "l"(gp), "f"(a), "f"(b), "f"(c), "f"(d) : "memory");
}
__device__ __forceinline__ void red2(float* gp, float a, float b) {
    asm volatile(
        "{\n\t.reg .u64 p;\n\t"
        "cvta.to.global.u64 p, %0;\n\t"
        "red.global.add.v2.f32 [p], {%1, %2};\n\t}"
        :: "l"(gp), "f"(a), "f"(b) : "memory");
}

// --------------------------------------------------------------------------
// phase-1 bodies (256-thread blocks)
// --------------------------------------------------------------------------
__device__ __forceinline__ void tail_body(const float* __restrict__ Wlin) {
    const int tid = threadIdx.x;
    const int wid = tid >> 5;
    const int lane = tid & 31;
    // slin (warps 0..5)
    if (wid < JD) {
        const float4* p = (const float4*)(Wlin + wid * N_DIM);
        float s = 0.0f;
        for (int q = lane; q < N_DIM / 4; q += 32) {
            float4 v = p[q];
            s += v.x + v.y + v.z + v.w;
        }
        #pragma unroll
        for (int o = 16; o; o >>= 1) s += __shfl_xor_sync(0xffffffffu, s, o);
        if (lane == 0) g_slin[wid] = s;
    }
    // re-zero g_v for this call's phase2 reds (previous dot already consumed it)
    float4* v4 = (float4*)g_v;
    const float4 z = make_float4(0.f, 0.f, 0.f, 0.f);
    for (int idx = tid; idx < JD * N_DIM / 4; idx += NTHR)
        v4[idx] = z;
}

template<int RPS_>
__device__ __forceinline__ void splitk_body(const float* __restrict__ big,
                                            const float* __restrict__ w,
                                            float* __restrict__ out,
                                            int cslab, int split,
                                            float (*ws)[RPS_]) {
    const int tid = threadIdx.x;
    const int c0 = cslab * 1024 + tid * 4;
    const int r0 = split * RPS_;

    for (int idx = tid; idx < JD * RPS_; idx += NTHR) {
        int j = idx / RPS_, rr = idx % RPS_;
        ws[j][rr] = w[j * N_DIM + r0 + rr];
    }
    __syncthreads();

    u64 acc[JD][2];
    #pragma unroll
    for (int j = 0; j < JD; j++) { acc[j][0] = 0ull; acc[j][1] = 0ull; }

    const ulonglong2* bp = (const ulonglong2*)big + (((size_t)r0 * N_DIM + c0) >> 2);
    #pragma unroll 8
    for (int rr = 0; rr < RPS_; rr++) {
        ulonglong2 d = bp[(size_t)rr * (N_DIM / 4)];
        #pragma unroll
        for (int j = 0; j < JD; j++) {
            u64 wp = pk2(ws[j][rr], ws[j][rr]);
            fma2(acc[j][0], d.x, wp);
            fma2(acc[j][1], d.y, wp);
        }
    }

    #pragma unroll
    for (int j = 0; j < JD; j++) {
        float2 a = upk(acc[j][0]), b = upk(acc[j][1]);
        red4(out + j * N_DIM + c0, a.x, a.y, b.x, b.y);
    }
}

// row-GEMV: 16 rows (8 warps x 2 rows) x CPK cols, KSPLIT col splits.
// TO_OUT=false: write partials to partbase[ks][row][j].
// TO_OUT=true : red.v2 scaled partials (x 1/64) straight into out[row][j].
template<bool TO_OUT>
__device__ __forceinline__ void rowgemv_body(const float* __restrict__ big,
                                             const float* __restrict__ S,
                                             float* __restrict__ dst,
                                             int rowblk, int ks,
                                             ulonglong2 (*ss)[CPK / 4]) {
    const int tid = threadIdx.x;
    const int wid = tid >> 5;
    const int lane = tid & 31;
    const int cbase = ks * CPK;
    const int r0 = rowblk * RGROWS + wid * 2;

    for (int idx = tid; idx < JD * (CPK / 4); idx += NTHR) {
        int j = idx >> 7, q = idx & 127;
        ss[j][q] = ((const ulonglong2*)(S + j * N_DIM + cbase))[q];
    }
    __syncthreads();

    u64 a0[JD], a1[JD];
    #pragma unroll
    for (int j = 0; j < JD; j++) { a0[j] = 0ull; a1[j] = 0ull; }

    const ulonglong2* b0 = (const ulonglong2*)(big + (size_t)r0 * N_DIM + cbase);
    const ulonglong2* b1 = (const ulonglong2*)(big + (size_t)(r0 + 1) * N_DIM + cbase);

    #pragma unroll
    for (int it = 0; it < CPK / 128; it++) {     // 4 iterations
        const int q = it * 32 + lane;
        ulonglong2 m0 = b0[q], m1 = b1[q];
        #pragma unroll
        for (int j = 0; j < JD; j++) {
            ulonglong2 sv = ss[j][q];
            fma2(a0[j], m0.x, sv.x); fma2(a0[j], m0.y, sv.y);
            fma2(a1[j], m1.x, sv.x); fma2(a1[j], m1.y, sv.y);
        }
    }

    #pragma unroll
    for (int j = 0; j < JD; j++) {
        #pragma unroll
        for (int o = 16; o; o >>= 1) {
            add2(a0[j], __shfl_xor_sync(0xffffffffu, a0[j], o));
            add2(a1[j], __shfl_xor_sync(0xffffffffu, a1[j], o));
        }
    }

    if (lane == 0) {
        if (TO_OUT) {
            float* o0 = dst + (size_t)r0 * JD;
            float* o1 = o0 + JD;
            #pragma unroll
            for (int p = 0; p < 3; p++) {
                float2 e0 = upk(a0[2 * p]), e1 = upk(a0[2 * p + 1]);
                float2 g0 = upk(a1[2 * p]), g1 = upk(a1[2 * p + 1]);
                red2(o0 + 2 * p, (e0.x + e0.y) * OUT_SCALE, (e1.x + e1.y) * OUT_SCALE);
                red2(o1 + 2 * p, (g0.x + g0.y) * OUT_SCALE, (g1.x + g1.y) * OUT_SCALE);
            }
        } else {
            float* p = dst + (size_t)ks * (N_DIM * JD);
            #pragma unroll
            for (int j = 0; j < JD; j++) {
                float2 f0 = upk(a0[j]), f1 = upk(a1[j]);
                p[(size_t)r0 * JD + j] = f0.x + f0.y;
                p[(size_t)(r0 + 1) * JD + j] = f1.x + f1.y;
            }
        }
    }
}

// --------------------------------------------------------------------------
// Phase 1: T-splitk (red.v4 into g_T) + k-rowgemv (partials) + slin/g_v-zero.
// --------------------------------------------------------------------------
__global__ void __launch_bounds__(NTHR) phase1_kernel(
        const float* __restrict__ data_q, const float* __restrict__ W_lin,
        const float* __restrict__ W_k,    const float* __restrict__ data_k) {
    __shared__ ulonglong2 ss[JD][CPK / 4];   // 12KB (splitk aliases as ws)
    const int bid = blockIdx.x;
    if (bid < SPLITK_T_BLOCKS) {
        splitk_body<RPS_T>(data_q, W_lin, g_T, bid & 3, bid >> 2, (float (*)[RPS_T])ss);
    } else if (bid < SPLITK_T_BLOCKS + RG_BLOCKS) {
        const int rb = bid - SPLITK_T_BLOCKS;
        rowgemv_body<false>(W_k, data_k, g_rgpart, rb >> 3, rb & 7, ss);
    } else {
        tail_body(W_lin);
    }
}

// --------------------------------------------------------------------------
// Phase 2: fused nq -> kmod -> v over ONE DRAM streaming of W_q (sweep C hits
// L2). 128 blocks x 512 threads, 32 rows/block, 8 cols/thread.
// --------------------------------------------------------------------------
__global__ void __launch_bounds__(512) phase2_kernel(
        const float* __restrict__ Wq,  const float* __restrict__ b_q,
        const float* __restrict__ b_k, const float* __restrict__ b_lin) {
    __shared__ float nqw[16][P2_ROWS][JD];   // [warp][row][j], 12KB
    __shared__ float kmod_s[P2_ROWS][JD];

    const int tid = threadIdx.x;
    const int w = tid >> 5;
    const int lane = tid & 31;
    const int r0 = blockIdx.x * P2_ROWS;
    const int cu = tid * 2;                  // ulonglong2 index (8 cols/thread)

    // T chunk packed by j-pairs: Tp[p][c] = (T[2p][col], T[2p+1][col])
    u64 Tp[3][8];
    #pragma unroll
    for (int p = 0; p < 3; p++) {
        const float4* e4 = (const float4*)(g_T + (2 * p) * N_DIM);
        const float4* o4 = (const float4*)(g_T + (2 * p + 1) * N_DIM);
        float4 e0 = e4[tid * 2], e1 = e4[tid * 2 + 1];
        float4 o0 = o4[tid * 2], o1 = o4[tid * 2 + 1];
        Tp[p][0] = pk2(e0.x, o0.x); Tp[p][1] = pk2(e0.y, o0.y);
        Tp[p][2] = pk2(e0.z, o0.z); Tp[p][3] = pk2(e0.w, o0.w);
        Tp[p][4] = pk2(e1.x, o1.x); Tp[p][5] = pk2(e1.y, o1.y);
        Tp[p][6] = pk2(e1.z, o1.z); Tp[p][7] = pk2(e1.w, o1.w);
    }

    // ---- Sweep A: nq partial dots (streams the block's 32 rows of W_q) ----
    const ulonglong2* wrow = (const ulonglong2*)(Wq + (size_t)r0 * N_DIM) + cu;
    #pragma unroll 2
    for (int rr = 0; rr < P2_ROWS; rr++) {
        ulonglong2 m0 = wrow[0], m1 = wrow[1];
        wrow += N_DIM / 4;
        float2 f0 = upk(m0.x), f1 = upk(m0.y), f2 = upk(m1.x), f3 = upk(m1.y);
        u64 mm[8];
        mm[0] = pk2(f0.x, f0.x); mm[1] = pk2(f0.y, f0.y);
        mm[2] = pk2(f1.x, f1.x); mm[3] = pk2(f1.y, f1.y);
        mm[4] = pk2(f2.x, f2.x); mm[5] = pk2(f2.y, f2.y);
        mm[6] = pk2(f3.x, f3.x); mm[7] = pk2(f3.y, f3.y);

        u64 acc[3] = {0ull, 0ull, 0ull};
        #pragma unroll
        for (int p = 0; p < 3; p++)
            #pragma unroll
            for (int c = 0; c < 8; c++)
                fma2(acc[p], mm[c], Tp[p][c]);

        #pragma unroll
        for (int p = 0; p < 3; p++) {
            #pragma unroll
            for (int o = 16; o; o >>= 1)
                add2(acc[p], __shfl_xor_sync(0xffffffffu, acc[p], o));
        }
        if (lane == 0) {
            #pragma unroll
            for (int p = 0; p < 3; p++) {
                float2 f = upk(acc[p]);
                nqw[w][rr][2 * p] = f.x;
                nqw[w][rr][2 * p + 1] = f.y;
            }
        }
    }
    __syncthreads();

    // ---- Phase B: finalize k (from phase1 partials), nq -> kmod ----
    if (tid < P2_ROWS * JD) {
        const int rr = tid & 31;
        const int j = tid >> 5;
        const int m = r0 + rr;
        float nq = 0.f;
        #pragma unroll
        for (int ww = 0; ww < 16; ww++) nq += nqw[ww][rr][j];
        nq += b_q[m] * g_slin[j] + b_lin[j];
        float kv = 0.f;
        #pragma unroll
        for (int ks = 0; ks < KSPLIT; ks++)
            kv += g_rgpart[((size_t)ks * N_DIM + m) * JD + j];
        kv += b_k[m];
        float x = fmaf(kv, kv, 2.0f * kv) + nq * (1.0f + fabsf(kv));
        kmod_s[rr][j] = fminf(fmaxf(x, 0.0f), 6.0f);
    }
    __syncthreads();

    // ---- Sweep C: v accumulation (re-reads the same 32 rows; L2-resident) ----
    u64 vp[3][8];
    #pragma unroll
    for (int p = 0; p < 3; p++)
        #pragma unroll
        for (int c = 0; c < 8; c++) vp[p][c] = 0ull;

    wrow = (const ulonglong2*)(Wq + (size_t)r0 * N_DIM) + cu;
    #pragma unroll 2
    for (int rr = 0; rr < P2_ROWS; rr++) {
        ulonglong2 m0 = wrow[0], m1 = wrow[1];
        wrow += N_DIM / 4;
        float2 f0 = upk(m0.x), f1 = upk(m0.y), f2 = upk(m1.x), f3 = upk(m1.y);
        u64 mm[8];
        mm[0] = pk2(f0.x, f0.x); mm[1] = pk2(f0.y, f0.y);
        mm[2] = pk2(f1.x, f1.x); mm[3] = pk2(f1.y, f1.y);
        mm[4] = pk2(f2.x, f2.x); mm[5] = pk2(f2.y, f2.y);
        mm[6] = pk2(f3.x, f3.x); mm[7] = pk2(f3.y, f3.y);

        u64 km[3];
        #pragma unroll
        for (int p = 0; p < 3; p++) km[p] = pk2(kmod_s[rr][2 * p], kmod_s[rr][2 * p + 1]);

        #pragma unroll
        for (int p = 0; p < 3; p++)
            #pragma unroll
            for (int c = 0; c < 8; c++)
                fma2(vp[p][c], mm[c], km[p]);
    }

    // atomically accumulate v: thread owns cols c0..c0+7 for all 6 j
    const int c0 = tid * 8;
    #pragma unroll
    for (int p = 0; p < 3; p++) {
        float2 u0 = upk(vp[p][0]), u1 = upk(vp[p][1]), u2 = upk(vp[p][2]), u3 = upk(vp[p][3]);
        float2 u4 = upk(vp[p][4]), u5 = upk(vp[p][5]), u6 = upk(vp[p][6]), u7 = upk(vp[p][7]);
        float* ev = g_v + (2 * p) * N_DIM + c0;
        float* ov = g_v + (2 * p + 1) * N_DIM + c0;
        red4(ev + 0, u0.x, u1.x, u2.x, u3.x);
        red4(ev + 4, u4.x, u5.x, u6.x, u7.x);
        red4(ov + 0, u0.y, u1.y, u2.y, u3.y);
        red4(ov + 4, u4.y, u5.y, u6.y, u7.y);
    }

    // c partials: c[j] = sum_rr b_q[r0+rr] * kmod[rr][j]
    if (tid < JD) {
        float s = 0.f;
        #pragma unroll
        for (int rr = 0; rr < P2_ROWS; rr++)
            s += b_q[r0 + rr] * kmod_s[rr][tid];
        g_cpart[blockIdx.x * JD + tid] = s;
    }
}

// --------------------------------------------------------------------------
// init_out: c[j] = sum_b cpart[b][j] (parallel tree), out[m][j] = c[j]/64 for
// all rows (dot reds scaled partials on top). Also zeroes g_T for next call.
// 32 blocks x 256 threads.
// --------------------------------------------------------------------------
__global__ void __launch_bounds__(NTHR) init_out_kernel(float* __restrict__ out) {
    __shared__ float red[128][JD];
    __shared__ float cs[JD];
    const int tid = threadIdx.x;

    if (tid < 128) {
        const float* cp = g_cpart + tid * JD;
        #pragma unroll
        for (int j = 0; j < JD; j++) red[tid][j] = cp[j];
    }
    __syncthreads();
    for (int s = 64; s > 0; s >>= 1) {
        if (tid < s) {
            #pragma unroll
            for (int j = 0; j < JD; j++) red[tid][j] += red[tid + s][j];
        }
        __syncthreads();
    }
    if (tid < JD) cs[tid] = red[0][tid] * OUT_SCALE;
    __syncthreads();

    // write out rows (4096 rows / 32 blocks = 128 rows per block)
    const int m0 = blockIdx.x * 128;
    for (int r = tid; r < 128; r += NTHR) {
        float* o = out + (size_t)(m0 + r) * JD;
        #pragma unroll
        for (int j = 0; j < JD; j++) o[j] = cs[j];
    }

    // zero g_T for the next invocation (phase2 of this call already read it)
    const int gt = blockIdx.x * NTHR + tid;              // 8192 threads
    float4* t4 = (float4*)g_T;
    const float4 z = make_float4(0.f, 0.f, 0.f, 0.f);
    for (int idx = gt; idx < JD * N_DIM / 4; idx += 32 * NTHR)
        t4[idx] = z;
}

// dot pass: data_q x g_v, scaled red.v2 straight into out
__global__ void __launch_bounds__(NTHR) dot_kernel(const float* __restrict__ data_q,
                                                   float* __restrict__ out) {
    __shared__ ulonglong2 ss[JD][CPK / 4];
    rowgemv_body<true>(data_q, g_v, out, blockIdx.x, blockIdx.y, ss);
}

// --------------------------------------------------------------------------
extern "C" void kernel_launch(void* const* d_in, const int* in_sizes, int n_in,
                              void* d_out, int out_size) {
    const float* data_q = (const float*)d_in[0];   // [4096,4096]
    const float* data_k = (const float*)d_in[1];   // [6,4096]
    const float* W_q    = (const float*)d_in[2];   // [4096,4096]
    const float* b_q    = (const float*)d_in[3];   // [4096]
    const float* W_lin  = (const float*)d_in[4];   // [6,4096]
    const float* b_lin  = (const float*)d_in[5];   // [6]
    const float* W_k    = (const float*)d_in[6];   // [4096,4096]
    const float* b_k    = (const float*)d_in[7];   // [4096]
    float* out = (float*)d_out;                    // [4096,6]

    phase1_kernel<<<SPLITK_T_BLOCKS + RG_BLOCKS + 1, NTHR>>>(data_q, W_lin, W_k, data_k);
    phase2_kernel<<<P2_BLOCKS, 512>>>(W_q, b_q, b_k, b_lin);     // nq+kmod+v+c, W_q once
    init_out_kernel<<<32, NTHR>>>(out);                          // out=c/64, zero g_T
    dot_kernel<<<dim3(RGX, KSPLIT), NTHR>>>(data_q, out);        // red dot/64 into out
}